// round 1
// baseline (speedup 1.0000x reference)
#include <cuda_runtime.h>
#include <cuda_bf16.h>

// Problem constants
#define B_   64
#define N_   200000
#define R_   4
#define V_   64          // R^3
#define CLS_ 40
#define BINS_ 65         // 64 real + 1 dummy (out-of-range)

// Histogram launch geometry: 16 chunks per batch, 256 threads/block.
// 200000 / 16 = 12500 points per block = 3125 groups of 4 points (exact).
#define CHUNKS_ 16
#define PTS_PER_BLK_ (N_ / CHUNKS_)          // 12500
#define GRPS_PER_BLK_ (PTS_PER_BLK_ / 4)     // 3125
#define HTHREADS_ 256

// Scratch: per-batch integer counts (65 bins each). No cudaMalloc allowed.
__device__ int g_counts[B_ * BINS_];

__global__ void zero_counts_kernel() {
    int i = blockIdx.x * 256 + threadIdx.x;
    if (i < B_ * BINS_) g_counts[i] = 0;
}

__global__ __launch_bounds__(HTHREADS_) void hist_kernel(const float* __restrict__ x) {
    __shared__ int sh[BINS_];

    const int b = blockIdx.y;
    const int chunk = blockIdx.x;

    for (int i = threadIdx.x; i < BINS_; i += HTHREADS_) sh[i] = 0;
    __syncthreads();

    // Base of this block's contiguous slice: 12500 points * 3 floats, 48B-group aligned.
    const float4* __restrict__ base = reinterpret_cast<const float4*>(
        x + ((size_t)b * N_ + (size_t)chunk * PTS_PER_BLK_) * 3);

    for (int g = threadIdx.x; g < GRPS_PER_BLK_; g += HTHREADS_) {
        // 4 points = 12 floats = 3 float4 loads
        const float4 a = base[g * 3 + 0];
        const float4 c = base[g * 3 + 1];
        const float4 d = base[g * 3 + 2];

        float px[4], py[4], pz[4];
        px[0] = a.x; py[0] = a.y; pz[0] = a.z;
        px[1] = a.w; py[1] = c.x; pz[1] = c.y;
        px[2] = c.z; py[2] = c.w; pz[2] = d.x;
        px[3] = d.y; py[3] = d.z; pz[3] = d.w;

#pragma unroll
        for (int p = 0; p < 4; p++) {
            const float x0 = px[p], x1 = py[p], x2 = pz[p];
            // floor per coordinate (valid range gives i in [-2,1])
            const int i0 = __float2int_rd(x0);
            const int i1 = __float2int_rd(x1);
            const int i2 = __float2int_rd(x2);
            // bin = (i0+2)*16 + (i1+2)*4 + (i2+2)  -> fold +42
            int bin = i0 * 16 + i1 * 4 + i2 + 42;
            // validity: max(|x0|,|x1|,|x2|) < 2  (strict: drops measure-zero
            // exact-boundary points; effect ~5e-6, well under tolerance, and
            // guarantees bin in [0,63])
            const float m = fmaxf(fmaxf(fabsf(x0), fabsf(x1)), fabsf(x2));
            bin = (m < 2.0f) ? bin : 64;   // dummy bin for out-of-range
            atomicAdd(&sh[bin], 1);
        }
    }

    __syncthreads();
    if (threadIdx.x < BINS_) {
        const int v = sh[threadIdx.x];
        if (v) atomicAdd(&g_counts[b * BINS_ + threadIdx.x], v);
    }
}

// One block per batch row: normalize counts and do the 64x40 GEMV.
__global__ __launch_bounds__(64) void out_kernel(const float* __restrict__ W,
                                                 const float* __restrict__ bias,
                                                 float* __restrict__ out) {
    __shared__ float cf[V_];
    const int b = blockIdx.x;
    const int t = threadIdx.x;

    cf[t] = (float)g_counts[b * BINS_ + t];   // t < 64: real bins only
    __syncthreads();

    float tot = 0.f;
#pragma unroll
    for (int v = 0; v < V_; v++) tot += cf[v];   // exact: integer sums < 2^24
    const float inv = 1.0f / tot;

    if (t < CLS_) {
        float acc = 0.f;
#pragma unroll
        for (int v = 0; v < V_; v++) acc += cf[v] * W[t * V_ + v];
        out[b * CLS_ + t] = acc * inv + bias[t];
    }
}

extern "C" void kernel_launch(void* const* d_in, const int* in_sizes, int n_in,
                              void* d_out, int out_size) {
    const float* x    = (const float*)d_in[0];   // [B, N, 3] f32
    const float* W    = (const float*)d_in[1];   // [CLASSES, V] f32
    const float* bias = (const float*)d_in[2];   // [CLASSES] f32
    float* out = (float*)d_out;                  // [B, CLASSES] f32

    zero_counts_kernel<<<(B_ * BINS_ + 255) / 256, 256>>>();
    hist_kernel<<<dim3(CHUNKS_, B_), HTHREADS_>>>(x);
    out_kernel<<<B_, 64>>>(W, bias, out);
}